// round 9
// baseline (speedup 1.0000x reference)
#include <cuda_runtime.h>
#include <cuda_fp16.h>
#include <math.h>

#define L 5
#define C 16
#define H 256
#define W 256
#define HW (H*W)
#define BN_EPS 1e-5f

typedef unsigned long long u64;

// ---- packed fp32x2 helpers (Blackwell FFMA2 path) ----
__device__ __forceinline__ u64 f2u(float2 v) {
    u64 r; asm("mov.b64 %0, {%1,%2};" : "=l"(r) : "f"(v.x), "f"(v.y)); return r;
}
__device__ __forceinline__ float2 u2f(u64 v) {
    float2 r; asm("mov.b64 {%0,%1}, %2;" : "=f"(r.x), "=f"(r.y) : "l"(v)); return r;
}
__device__ __forceinline__ float2 ffma2(float2 a, float2 b, float2 c) {
    u64 d;
    asm("fma.rn.f32x2 %0, %1, %2, %3;" : "=l"(d) : "l"(f2u(a)), "l"(f2u(b)), "l"(f2u(c)));
    return u2f(d);
}
__device__ __forceinline__ float2 fmul2(float2 a, float2 b) {
    u64 d;
    asm("mul.rn.f32x2 %0, %1, %2;" : "=l"(d) : "l"(f2u(a)), "l"(f2u(b)));
    return u2f(d);
}

// Folded parameters. All weight arrays 16B-aligned for LDS.128.
struct __align__(16) Params {
    float minv[L*L][8];
    float w1nb[16][16];
    float w1eg[16][16];
    float b1[16];
    float w2[8][16];
    float b2[8];
    float w3[4][8];
    float b3[4];
    float w4[4];
    float b4;
    float _pad[3];
    float wm[16][16];
    float bm[16];
};
__device__ Params g_p;

// HWC fp16 copy of x: per pixel, 16 channels = 32 bytes contiguous. 10.5 MB.
__device__ __half2 g_xt[(size_t)L * HW * 8];

// Fused transpose + param prep. Blocks [0, L*HW/256) transpose; last block preps.
__global__ __launch_bounds__(256)
void prep_transpose_kernel(
    const float* __restrict__ x,
    const float* __restrict__ ptm,
    const float* __restrict__ w1, const float* __restrict__ b1,
    const float* __restrict__ g1, const float* __restrict__ be1,
    const float* __restrict__ rm1, const float* __restrict__ rv1,
    const float* __restrict__ w2, const float* __restrict__ b2,
    const float* __restrict__ g2, const float* __restrict__ be2,
    const float* __restrict__ rm2, const float* __restrict__ rv2,
    const float* __restrict__ w3, const float* __restrict__ b3,
    const float* __restrict__ g3, const float* __restrict__ be3,
    const float* __restrict__ rm3, const float* __restrict__ rv3,
    const float* __restrict__ w4, const float* __restrict__ b4,
    const float* __restrict__ wm, const float* __restrict__ bm)
{
    if (blockIdx.x < (L*HW)/256) {
        // ---- CHW fp32 -> HWC fp16 transpose ----
        int idx = blockIdx.x * 256 + threadIdx.x;   // over L*HW
        int j   = idx >> 16;
        int hw  = idx & (HW - 1);
        const float* base = x + (size_t)j * C * HW + hw;

        __half2 v[8];
        #pragma unroll
        for (int k = 0; k < 8; k++) {
            float a = __ldg(base + (2*k)   * HW);
            float b = __ldg(base + (2*k+1) * HW);
            v[k] = __floats2half2_rn(a, b);
        }
        uint4* dst = reinterpret_cast<uint4*>(g_xt) + (size_t)idx * 2;
        dst[0] = reinterpret_cast<uint4*>(v)[0];
        dst[1] = reinterpret_cast<uint4*>(v)[1];
        return;
    }

    // ---- parameter folding (last block, 256 threads, strided over 768 slots) ----
    for (int t = threadIdx.x; t < 768; t += 256) {
        if (t < L*L) {
            const float* m = ptm + t*16;
            float a  = m[0], b = m[1], tx = m[3] * 1.25f;   // 1/(0.4*2)
            float c  = m[4], d = m[5], ty = m[7] * 1.25f;
            float inv = 1.0f / (a*d - b*c);
            float ia =  d*inv, ib = -b*inv;
            float ic = -c*inv, id =  a*inv;
            g_p.minv[t][0] = ia; g_p.minv[t][1] = ib; g_p.minv[t][2] = -(ia*tx + ib*ty);
            g_p.minv[t][3] = ic; g_p.minv[t][4] = id; g_p.minv[t][5] = -(ic*tx + id*ty);
            g_p.minv[t][6] = 0.f; g_p.minv[t][7] = 0.f;
        }
        if (t >= 32 && t < 288) {
            int idx2 = t - 32, o = idx2 >> 4, c2 = idx2 & 15;
            float sc = g1[o] * rsqrtf(rv1[o] + BN_EPS);
            g_p.w1nb[o][c2] = w1[o*32 + c2]      * sc;
            g_p.w1eg[o][c2] = w1[o*32 + 16 + c2] * sc;
            if (c2 == 0) g_p.b1[o] = (b1[o] - rm1[o]) * sc + be1[o];
        }
        if (t >= 288 && t < 416) {
            int idx2 = t - 288, o = idx2 >> 4, c2 = idx2 & 15;
            float sc = g2[o] * rsqrtf(rv2[o] + BN_EPS);
            g_p.w2[o][c2] = w2[o*16 + c2] * sc;
            if (c2 == 0) g_p.b2[o] = (b2[o] - rm2[o]) * sc + be2[o];
        }
        if (t >= 416 && t < 448) {
            int idx2 = t - 416, o = idx2 >> 3, c2 = idx2 & 7;
            float sc = g3[o] * rsqrtf(rv3[o] + BN_EPS);
            g_p.w3[o][c2] = w3[o*8 + c2] * sc;
            if (c2 == 0) g_p.b3[o] = (b3[o] - rm3[o]) * sc + be3[o];
        }
        if (t >= 448 && t < 452) g_p.w4[t-448] = w4[t-448];
        if (t == 452) g_p.b4 = b4[0];
        if (t >= 512 && t < 768) {
            int idx2 = t - 512, o = idx2 >> 4, c2 = idx2 & 15;
            g_p.wm[o][c2] = wm[o*16 + c2];
            if (c2 == 0) g_p.bm[o] = bm[o];
        }
    }
}

// Accumulate one tap (16 ch as 2 x uint4 of half2) into nb2[8] with weight w.
__device__ __forceinline__ void acc_tap2(uint4 va, uint4 vb, float w, float2* nb2)
{
    float2 wv = make_float2(w, w);
    #pragma unroll
    for (int k = 0; k < 4; k++) {
        float2 f = __half22float2(reinterpret_cast<__half2*>(&va)[k]);
        nb2[k] = ffma2(wv, f, nb2[k]);
    }
    #pragma unroll
    for (int k = 0; k < 4; k++) {
        float2 f = __half22float2(reinterpret_cast<__half2*>(&vb)[k]);
        nb2[4+k] = ffma2(wv, f, nb2[4+k]);
    }
}

// dot of 16-wide weight row (float4-aligned in smem) with packed input pairs.
__device__ __forceinline__ float dot16(const float* row, const float2* in2, float bias)
{
    const float4* wr = reinterpret_cast<const float4*>(row);
    float2 a = make_float2(bias, 0.0f);
    #pragma unroll
    for (int q = 0; q < 4; q++) {
        float4 wv = wr[q];
        a = ffma2(make_float2(wv.x, wv.y), in2[2*q],   a);
        a = ffma2(make_float2(wv.z, wv.w), in2[2*q+1], a);
    }
    return a.x + a.y;
}

// Per-j tap addresses + bilinear weights.
struct Tap {
    const uint4* p[4];
    float w[4];
};

__device__ __forceinline__ Tap calc_tap(const float* mv, float wf, float hf,
                                        const uint4* jb)
{
    Tap t;
    float sx = fmaf(mv[0], wf, fmaf(mv[1], hf, mv[2]));
    float sy = fmaf(mv[3], wf, fmaf(mv[4], hf, mv[5]));
    float x0f = floorf(sx), y0f = floorf(sy);
    float fx = sx - x0f, fy = sy - y0f;
    float w00 = (1.0f-fx)*(1.0f-fy), w01 = fx*(1.0f-fy);
    float w10 = (1.0f-fx)*fy,        w11 = fx*fy;
    int x0 = (int)x0f, y0 = (int)y0f;
    bool vx0 = (x0   >= 0) && (x0   <= W-1);
    bool vx1 = (x0+1 >= 0) && (x0+1 <= W-1);
    bool vy0 = (y0   >= 0) && (y0   <= H-1);
    bool vy1 = (y0+1 >= 0) && (y0+1 <= H-1);
    t.w[0] = (vx0 && vy0) ? w00 : 0.0f;
    t.w[1] = (vx1 && vy0) ? w01 : 0.0f;
    t.w[2] = (vx0 && vy1) ? w10 : 0.0f;
    t.w[3] = (vx1 && vy1) ? w11 : 0.0f;
    int xi0 = min(max(x0,   0), W-1), xi1 = min(max(x0+1, 0), W-1);
    int yi0 = min(max(y0,   0), H-1), yi1 = min(max(y0+1, 0), H-1);
    t.p[0] = jb + (size_t)(yi0*W + xi0) * 2;
    t.p[1] = jb + (size_t)(yi0*W + xi1) * 2;
    t.p[2] = jb + (size_t)(yi1*W + xi0) * 2;
    t.p[3] = jb + (size_t)(yi1*W + xi1) * 2;
    return t;
}

__global__ __launch_bounds__(128)
void DiscoNetFusion_kernel(float* __restrict__ out)
{
    __shared__ Params sp;
    {
        const float4* src = (const float4*)&g_p;
        float4* dst = (float4*)&sp;
        const int n = sizeof(Params) / 16;
        for (int k = threadIdx.x; k < n; k += blockDim.x) dst[k] = src[k];
    }
    __syncthreads();

    const int i  = blockIdx.y;                          // ego agent
    const int hw = blockIdx.x * blockDim.x + threadIdx.x;
    const float wf = (float)(hw & (W-1));
    const float hf = (float)(hw >> 8);

    const uint4* xt = reinterpret_cast<const uint4*>(g_xt);

    // ---- issue ego pixel loads (fp16 HWC, 2 x LDG.128) ----
    const uint4* pe = xt + (size_t)(i*HW + hw) * 2;
    uint4 e0 = __ldg(pe), e1 = __ldg(pe + 1);

    // ---- issue j=0 tap loads ----
    Tap tc = calc_tap(sp.minv[0*L + i], wf, hf, xt);   // j=0 base: xt + 0
    uint4 curA[4], curB[4];
    #pragma unroll
    for (int t = 0; t < 4; t++) { curA[t] = __ldg(tc.p[t]); curB[t] = __ldg(tc.p[t] + 1); }
    float wcur[4] = { tc.w[0], tc.w[1], tc.w[2], tc.w[3] };

    // ---- ego precompute (overlaps j=0 tap latency) ----
    float ego[16];
    {
        float2 xi2[8];
        #pragma unroll
        for (int k = 0; k < 4; k++)
            xi2[k] = __half22float2(reinterpret_cast<__half2*>(&e0)[k]);
        #pragma unroll
        for (int k = 0; k < 4; k++)
            xi2[4+k] = __half22float2(reinterpret_cast<__half2*>(&e1)[k]);
        #pragma unroll
        for (int o = 0; o < 16; o++)
            ego[o] = dot16(sp.w1eg[o], xi2, sp.b1[o]);
    }

    // ---- online softmax state ----
    float mrun = -1e30f, srun = 0.0f;
    float2 acc2[8];
    #pragma unroll
    for (int k = 0; k < 8; k++) acc2[k] = make_float2(0.f, 0.f);

    // ---- software-pipelined j loop ----
    #pragma unroll
    for (int j = 0; j < L; j++) {
        uint4 nxtA[4], nxtB[4];
        float wnxt[4];
        if (j + 1 < L) {
            Tap tn = calc_tap(sp.minv[(j+1)*L + i], wf, hf,
                              xt + (size_t)(j+1) * HW * 2);
            #pragma unroll
            for (int t = 0; t < 4; t++) {
                nxtA[t] = __ldg(tn.p[t]); nxtB[t] = __ldg(tn.p[t] + 1);
                wnxt[t] = tn.w[t];
            }
        }

        // consume current taps
        float2 nb2[8];
        #pragma unroll
        for (int k = 0; k < 8; k++) nb2[k] = make_float2(0.f, 0.f);
        #pragma unroll
        for (int t = 0; t < 4; t++) acc_tap2(curA[t], curB[t], wcur[t], nb2);

        // ---- tiny MLP -> logit ----
        float2 h1p[8];
        #pragma unroll
        for (int o = 0; o < 8; o++) {
            float a = fmaxf(dot16(sp.w1nb[2*o],   nb2, ego[2*o]),   0.0f);
            float b = fmaxf(dot16(sp.w1nb[2*o+1], nb2, ego[2*o+1]), 0.0f);
            h1p[o] = make_float2(a, b);
        }
        float2 h2p[4];
        #pragma unroll
        for (int o = 0; o < 4; o++) {
            float a = fmaxf(dot16(sp.w2[2*o],   h1p, sp.b2[2*o]),   0.0f);
            float b = fmaxf(dot16(sp.w2[2*o+1], h1p, sp.b2[2*o+1]), 0.0f);
            h2p[o] = make_float2(a, b);
        }
        float2 h3p[2];
        #pragma unroll
        for (int o = 0; o < 4; o++) {
            const float4* wr = reinterpret_cast<const float4*>(sp.w3[o]);
            float2 a = make_float2(sp.b3[o], 0.0f);
            float4 w0 = wr[0], w1v = wr[1];
            a = ffma2(make_float2(w0.x,  w0.y),  h2p[0], a);
            a = ffma2(make_float2(w0.z,  w0.w),  h2p[1], a);
            a = ffma2(make_float2(w1v.x, w1v.y), h2p[2], a);
            a = ffma2(make_float2(w1v.z, w1v.w), h2p[3], a);
            float v = fmaxf(a.x + a.y, 0.0f);
            if (o & 1) h3p[o>>1].y = v; else h3p[o>>1].x = v;
        }
        float2 lg2 = make_float2(sp.b4, 0.0f);
        lg2 = ffma2(make_float2(sp.w4[0], sp.w4[1]), h3p[0], lg2);
        lg2 = ffma2(make_float2(sp.w4[2], sp.w4[3]), h3p[1], lg2);
        float lg = fmaxf(lg2.x + lg2.y, 0.0f);

        // ---- online softmax accumulate ----
        float mn  = fmaxf(mrun, lg);
        float scl = __expf(mrun - mn);
        float p   = __expf(lg - mn);
        srun = srun * scl + p;
        float2 sv = make_float2(scl, scl), pv = make_float2(p, p);
        #pragma unroll
        for (int k = 0; k < 8; k++)
            acc2[k] = ffma2(acc2[k], sv, fmul2(pv, nb2[k]));
        mrun = mn;

        // rotate pipeline registers (renamed away by unroll)
        if (j + 1 < L) {
            #pragma unroll
            for (int t = 0; t < 4; t++) {
                curA[t] = nxtA[t]; curB[t] = nxtB[t]; wcur[t] = wnxt[t];
            }
        }
    }

    const float invs = 1.0f / srun;
    float2 iv = make_float2(invs, invs);
    #pragma unroll
    for (int k = 0; k < 8; k++) acc2[k] = fmul2(acc2[k], iv);

    // ---- final 16x16 channel mix + bias ----
    #pragma unroll
    for (int o = 0; o < 16; o++)
        out[(i*C + o)*HW + hw] = dot16(sp.wm[o], acc2, sp.bm[o]);
}

extern "C" void kernel_launch(void* const* d_in, const int* in_sizes, int n_in,
                              void* d_out, int out_size)
{
    (void)in_sizes; (void)n_in; (void)out_size;
    const float* x   = (const float*)d_in[0];
    // d_in[1] = record_len (unused)
    const float* ptm = (const float*)d_in[2];

    prep_transpose_kernel<<<(L*HW)/256 + 1, 256>>>(x, ptm,
        (const float*)d_in[3],  (const float*)d_in[4],  (const float*)d_in[5],
        (const float*)d_in[6],  (const float*)d_in[7],  (const float*)d_in[8],
        (const float*)d_in[9],  (const float*)d_in[10], (const float*)d_in[11],
        (const float*)d_in[12], (const float*)d_in[13], (const float*)d_in[14],
        (const float*)d_in[15], (const float*)d_in[16], (const float*)d_in[17],
        (const float*)d_in[18], (const float*)d_in[19], (const float*)d_in[20],
        (const float*)d_in[21], (const float*)d_in[22],
        (const float*)d_in[23], (const float*)d_in[24]);

    dim3 grid(HW / 128, L);
    DiscoNetFusion_kernel<<<grid, 128>>>((float*)d_out);
}

// round 12
// speedup vs baseline: 2.3438x; 2.3438x over previous
#include <cuda_runtime.h>
#include <cuda_fp16.h>
#include <math.h>

#define L 5
#define C 16
#define H 256
#define W 256
#define HW (H*W)
#define BN_EPS 1e-5f

typedef unsigned long long u64;

// ---- packed fp32x2 helpers (Blackwell FFMA2 path) ----
__device__ __forceinline__ u64 f2u(float2 v) {
    u64 r; asm("mov.b64 %0, {%1,%2};" : "=l"(r) : "f"(v.x), "f"(v.y)); return r;
}
__device__ __forceinline__ float2 u2f(u64 v) {
    float2 r; asm("mov.b64 {%0,%1}, %2;" : "=f"(r.x), "=f"(r.y) : "l"(v)); return r;
}
__device__ __forceinline__ float2 ffma2(float2 a, float2 b, float2 c) {
    u64 d;
    asm("fma.rn.f32x2 %0, %1, %2, %3;" : "=l"(d) : "l"(f2u(a)), "l"(f2u(b)), "l"(f2u(c)));
    return u2f(d);
}
__device__ __forceinline__ float2 fmul2(float2 a, float2 b) {
    u64 d;
    asm("mul.rn.f32x2 %0, %1, %2;" : "=l"(d) : "l"(f2u(a)), "l"(f2u(b)));
    return u2f(d);
}

// Folded parameters. All weight arrays 16B-aligned for LDS.128.
struct __align__(16) Params {
    float minv[L*L][8];
    float w1nb[16][16];
    float w1eg[16][16];
    float b1[16];
    float w2[8][16];
    float b2[8];
    float w3[4][8];
    float b3[4];
    float w4[4];
    float b4;
    float _pad[3];
    float wm[16][16];
    float bm[16];
};
__device__ Params g_p;

// HWC fp16 copy of x: per pixel, 16 channels = 32 bytes contiguous. 10.5 MB.
__device__ __half2 g_xt[(size_t)L * HW * 8];

// Fused transpose + param prep. Blocks [0, L*HW/256) transpose; last block preps.
__global__ __launch_bounds__(256)
void prep_transpose_kernel(
    const float* __restrict__ x,
    const float* __restrict__ ptm,
    const float* __restrict__ w1, const float* __restrict__ b1,
    const float* __restrict__ g1, const float* __restrict__ be1,
    const float* __restrict__ rm1, const float* __restrict__ rv1,
    const float* __restrict__ w2, const float* __restrict__ b2,
    const float* __restrict__ g2, const float* __restrict__ be2,
    const float* __restrict__ rm2, const float* __restrict__ rv2,
    const float* __restrict__ w3, const float* __restrict__ b3,
    const float* __restrict__ g3, const float* __restrict__ be3,
    const float* __restrict__ rm3, const float* __restrict__ rv3,
    const float* __restrict__ w4, const float* __restrict__ b4,
    const float* __restrict__ wm, const float* __restrict__ bm)
{
    if (blockIdx.x < (L*HW)/256) {
        int idx = blockIdx.x * 256 + threadIdx.x;   // over L*HW
        int j   = idx >> 16;
        int hw  = idx & (HW - 1);
        const float* base = x + (size_t)j * C * HW + hw;

        __half2 v[8];
        #pragma unroll
        for (int k = 0; k < 8; k++) {
            float a = __ldg(base + (2*k)   * HW);
            float b = __ldg(base + (2*k+1) * HW);
            v[k] = __floats2half2_rn(a, b);
        }
        uint4* dst = reinterpret_cast<uint4*>(g_xt) + (size_t)idx * 2;
        dst[0] = reinterpret_cast<uint4*>(v)[0];
        dst[1] = reinterpret_cast<uint4*>(v)[1];
        return;
    }

    // ---- parameter folding (last block) ----
    for (int t = threadIdx.x; t < 768; t += 256) {
        if (t < L*L) {
            const float* m = ptm + t*16;
            float a  = m[0], b = m[1], tx = m[3] * 1.25f;   // 1/(0.4*2)
            float c  = m[4], d = m[5], ty = m[7] * 1.25f;
            float inv = 1.0f / (a*d - b*c);
            float ia =  d*inv, ib = -b*inv;
            float ic = -c*inv, id =  a*inv;
            g_p.minv[t][0] = ia; g_p.minv[t][1] = ib; g_p.minv[t][2] = -(ia*tx + ib*ty);
            g_p.minv[t][3] = ic; g_p.minv[t][4] = id; g_p.minv[t][5] = -(ic*tx + id*ty);
            g_p.minv[t][6] = 0.f; g_p.minv[t][7] = 0.f;
        }
        if (t >= 32 && t < 288) {
            int idx2 = t - 32, o = idx2 >> 4, c2 = idx2 & 15;
            float sc = g1[o] * rsqrtf(rv1[o] + BN_EPS);
            g_p.w1nb[o][c2] = w1[o*32 + c2]      * sc;
            g_p.w1eg[o][c2] = w1[o*32 + 16 + c2] * sc;
            if (c2 == 0) g_p.b1[o] = (b1[o] - rm1[o]) * sc + be1[o];
        }
        if (t >= 288 && t < 416) {
            int idx2 = t - 288, o = idx2 >> 4, c2 = idx2 & 15;
            float sc = g2[o] * rsqrtf(rv2[o] + BN_EPS);
            g_p.w2[o][c2] = w2[o*16 + c2] * sc;
            if (c2 == 0) g_p.b2[o] = (b2[o] - rm2[o]) * sc + be2[o];
        }
        if (t >= 416 && t < 448) {
            int idx2 = t - 416, o = idx2 >> 3, c2 = idx2 & 7;
            float sc = g3[o] * rsqrtf(rv3[o] + BN_EPS);
            g_p.w3[o][c2] = w3[o*8 + c2] * sc;
            if (c2 == 0) g_p.b3[o] = (b3[o] - rm3[o]) * sc + be3[o];
        }
        if (t >= 448 && t < 452) g_p.w4[t-448] = w4[t-448];
        if (t == 452) g_p.b4 = b4[0];
        if (t >= 512 && t < 768) {
            int idx2 = t - 512, o = idx2 >> 4, c2 = idx2 & 15;
            g_p.wm[o][c2] = wm[o*16 + c2];
            if (c2 == 0) g_p.bm[o] = bm[o];
        }
    }
}

// Accumulate one tap (16 ch as 2 x uint4 of half2) into nb2[8] with weight w.
__device__ __forceinline__ void acc_tap2(uint4 va, uint4 vb, float w, float2* nb2)
{
    float2 wv = make_float2(w, w);
    #pragma unroll
    for (int k = 0; k < 4; k++) {
        float2 f = __half22float2(reinterpret_cast<__half2*>(&va)[k]);
        nb2[k] = ffma2(wv, f, nb2[k]);
    }
    #pragma unroll
    for (int k = 0; k < 4; k++) {
        float2 f = __half22float2(reinterpret_cast<__half2*>(&vb)[k]);
        nb2[4+k] = ffma2(wv, f, nb2[4+k]);
    }
}

// dot of 16-wide weight row (float4-aligned in smem) with packed input pairs.
__device__ __forceinline__ float dot16(const float* row, const float2* in2, float bias)
{
    const float4* wr = reinterpret_cast<const float4*>(row);
    float2 a = make_float2(bias, 0.0f);
    #pragma unroll
    for (int q = 0; q < 4; q++) {
        float4 wv = wr[q];
        a = ffma2(make_float2(wv.x, wv.y), in2[2*q],   a);
        a = ffma2(make_float2(wv.z, wv.w), in2[2*q+1], a);
    }
    return a.x + a.y;
}

// Per-j tap addresses + bilinear weights.
struct Tap {
    const uint4* p[4];
    float w[4];
};

__device__ __forceinline__ Tap calc_tap(const float* mv, float wf, float hf,
                                        const uint4* jb)
{
    Tap t;
    float sx = fmaf(mv[0], wf, fmaf(mv[1], hf, mv[2]));
    float sy = fmaf(mv[3], wf, fmaf(mv[4], hf, mv[5]));
    float x0f = floorf(sx), y0f = floorf(sy);
    float fx = sx - x0f, fy = sy - y0f;
    float w00 = (1.0f-fx)*(1.0f-fy), w01 = fx*(1.0f-fy);
    float w10 = (1.0f-fx)*fy,        w11 = fx*fy;
    int x0 = (int)x0f, y0 = (int)y0f;
    bool vx0 = (x0   >= 0) && (x0   <= W-1);
    bool vx1 = (x0+1 >= 0) && (x0+1 <= W-1);
    bool vy0 = (y0   >= 0) && (y0   <= H-1);
    bool vy1 = (y0+1 >= 0) && (y0+1 <= H-1);
    t.w[0] = (vx0 && vy0) ? w00 : 0.0f;
    t.w[1] = (vx1 && vy0) ? w01 : 0.0f;
    t.w[2] = (vx0 && vy1) ? w10 : 0.0f;
    t.w[3] = (vx1 && vy1) ? w11 : 0.0f;
    int xi0 = min(max(x0,   0), W-1), xi1 = min(max(x0+1, 0), W-1);
    int yi0 = min(max(y0,   0), H-1), yi1 = min(max(y0+1, 0), H-1);
    t.p[0] = jb + (size_t)(yi0*W + xi0) * 2;
    t.p[1] = jb + (size_t)(yi0*W + xi1) * 2;
    t.p[2] = jb + (size_t)(yi1*W + xi0) * 2;
    t.p[3] = jb + (size_t)(yi1*W + xi1) * 2;
    return t;
}

__global__ __launch_bounds__(256)
void DiscoNetFusion_kernel(float* __restrict__ out)
{
    __shared__ Params sp;
    {
        const float4* src = (const float4*)&g_p;
        float4* dst = (float4*)&sp;
        const int n = sizeof(Params) / 16;
        for (int k = threadIdx.x; k < n; k += blockDim.x) dst[k] = src[k];
    }
    __syncthreads();

    const int i  = blockIdx.y;
    const int hw = blockIdx.x * blockDim.x + threadIdx.x;
    const float wf = (float)(hw & (W-1));
    const float hf = (float)(hw >> 8);

    const uint4* xt = reinterpret_cast<const uint4*>(g_xt);

    // ---- prologue: issue ego + j=0 tap loads, then ego compute (overlap) ----
    const uint4* pe = xt + (size_t)(i*HW + hw) * 2;
    uint4 e0 = __ldg(pe), e1 = __ldg(pe + 1);

    float2 nbcur[8];          // carried: accumulated nb for the current j
    {
        Tap t0 = calc_tap(sp.minv[0*L + i], wf, hf, xt);
        uint4 rA[4], rB[4];
        #pragma unroll
        for (int t = 0; t < 4; t++) { rA[t] = __ldg(t0.p[t]); rB[t] = __ldg(t0.p[t] + 1); }

        // ego compute while loads are in flight
        float2 xi2[8];
        #pragma unroll
        for (int k = 0; k < 4; k++)
            xi2[k] = __half22float2(reinterpret_cast<__half2*>(&e0)[k]);
        #pragma unroll
        for (int k = 0; k < 4; k++)
            xi2[4+k] = __half22float2(reinterpret_cast<__half2*>(&e1)[k]);

        // stash ego in nbcur slot temporarily? No — compute into ego below.
        #pragma unroll
        for (int k = 0; k < 8; k++) nbcur[k] = make_float2(0.f, 0.f);
        // (ego computed after loads consumed; see below)
        // fold j=0 taps
        // first compute ego (uses xi2, no dependence on taps)
        // -- ego --
        float eg[16];
        #pragma unroll
        for (int o = 0; o < 16; o++)
            eg[o] = dot16(sp.w1eg[o], xi2, sp.b1[o]);
        // write ego to a local array the loop reads
        #pragma unroll
        for (int t = 0; t < 4; t++) acc_tap2(rA[t], rB[t], t0.w[t], nbcur);

        // ---- online softmax state ----
        float mrun = -1e30f, srun = 0.0f;
        float2 acc2[8];
        #pragma unroll
        for (int k = 0; k < 8; k++) acc2[k] = make_float2(0.f, 0.f);

        // ---- pipelined, rolled j loop ----
        #pragma unroll 1
        for (int j = 0; j < L; j++) {
            // issue next iteration's tap loads
            uint4 nA[4], nB[4];
            float wn[4];
            const bool has = (j + 1 < L);
            if (has) {
                Tap tn = calc_tap(sp.minv[(j+1)*L + i], wf, hf,
                                  xt + (size_t)(j+1) * HW * 2);
                #pragma unroll
                for (int t = 0; t < 4; t++) {
                    nA[t] = __ldg(tn.p[t]); nB[t] = __ldg(tn.p[t] + 1);
                    wn[t] = tn.w[t];
                }
            }

            // ---- MLP on nbcur (covers nA/nB latency) ----
            float2 h1p[8];
            #pragma unroll
            for (int o = 0; o < 8; o++) {
                float a = fmaxf(dot16(sp.w1nb[2*o],   nbcur, eg[2*o]),   0.0f);
                float b = fmaxf(dot16(sp.w1nb[2*o+1], nbcur, eg[2*o+1]), 0.0f);
                h1p[o] = make_float2(a, b);
            }
            float2 h2p[4];
            #pragma unroll
            for (int o = 0; o < 4; o++) {
                float a = fmaxf(dot16(sp.w2[2*o],   h1p, sp.b2[2*o]),   0.0f);
                float b = fmaxf(dot16(sp.w2[2*o+1], h1p, sp.b2[2*o+1]), 0.0f);
                h2p[o] = make_float2(a, b);
            }
            float2 h3p[2];
            #pragma unroll
            for (int o = 0; o < 4; o++) {
                const float4* wr = reinterpret_cast<const float4*>(sp.w3[o]);
                float2 a = make_float2(sp.b3[o], 0.0f);
                float4 w0 = wr[0], w1v = wr[1];
                a = ffma2(make_float2(w0.x,  w0.y),  h2p[0], a);
                a = ffma2(make_float2(w0.z,  w0.w),  h2p[1], a);
                a = ffma2(make_float2(w1v.x, w1v.y), h2p[2], a);
                a = ffma2(make_float2(w1v.z, w1v.w), h2p[3], a);
                float v = fmaxf(a.x + a.y, 0.0f);
                if (o & 1) h3p[o>>1].y = v; else h3p[o>>1].x = v;
            }
            float2 lg2 = make_float2(sp.b4, 0.0f);
            lg2 = ffma2(make_float2(sp.w4[0], sp.w4[1]), h3p[0], lg2);
            lg2 = ffma2(make_float2(sp.w4[2], sp.w4[3]), h3p[1], lg2);
            float lg = fmaxf(lg2.x + lg2.y, 0.0f);

            // ---- online softmax accumulate with nbcur ----
            float mn  = fmaxf(mrun, lg);
            float scl = __expf(mrun - mn);
            float p   = __expf(lg - mn);
            srun = srun * scl + p;
            float2 sv = make_float2(scl, scl), pv = make_float2(p, p);
            #pragma unroll
            for (int k = 0; k < 8; k++)
                acc2[k] = ffma2(acc2[k], sv, fmul2(pv, nbcur[k]));
            mrun = mn;

            // ---- rotate: fold next taps into nbcur, release raw regs ----
            if (has) {
                #pragma unroll
                for (int k = 0; k < 8; k++) nbcur[k] = make_float2(0.f, 0.f);
                #pragma unroll
                for (int t = 0; t < 4; t++) acc_tap2(nA[t], nB[t], wn[t], nbcur);
            }
        }

        const float invs = 1.0f / srun;
        float2 iv = make_float2(invs, invs);
        #pragma unroll
        for (int k = 0; k < 8; k++) acc2[k] = fmul2(acc2[k], iv);

        // ---- final 16x16 channel mix + bias ----
        #pragma unroll
        for (int o = 0; o < 16; o++)
            out[(i*C + o)*HW + hw] = dot16(sp.wm[o], acc2, sp.bm[o]);
    }
}

extern "C" void kernel_launch(void* const* d_in, const int* in_sizes, int n_in,
                              void* d_out, int out_size)
{
    (void)in_sizes; (void)n_in; (void)out_size;
    const float* x   = (const float*)d_in[0];
    // d_in[1] = record_len (unused)
    const float* ptm = (const float*)d_in[2];

    prep_transpose_kernel<<<(L*HW)/256 + 1, 256>>>(x, ptm,
        (const float*)d_in[3],  (const float*)d_in[4],  (const float*)d_in[5],
        (const float*)d_in[6],  (const float*)d_in[7],  (const float*)d_in[8],
        (const float*)d_in[9],  (const float*)d_in[10], (const float*)d_in[11],
        (const float*)d_in[12], (const float*)d_in[13], (const float*)d_in[14],
        (const float*)d_in[15], (const float*)d_in[16], (const float*)d_in[17],
        (const float*)d_in[18], (const float*)d_in[19], (const float*)d_in[20],
        (const float*)d_in[21], (const float*)d_in[22],
        (const float*)d_in[23], (const float*)d_in[24]);

    dim3 grid(HW / 256, L);
    DiscoNetFusion_kernel<<<grid, 256>>>((float*)d_out);
}

// round 14
// speedup vs baseline: 3.2379x; 1.3815x over previous
#include <cuda_runtime.h>
#include <cuda_fp16.h>
#include <math.h>

#define L 5
#define C 16
#define H 256
#define W 256
#define HW (H*W)
#define BN_EPS 1e-5f

typedef unsigned long long u64;

// ---- packed fp32x2 helpers (Blackwell FFMA2 path) ----
__device__ __forceinline__ u64 f2u(float2 v) {
    u64 r; asm("mov.b64 %0, {%1,%2};" : "=l"(r) : "f"(v.x), "f"(v.y)); return r;
}
__device__ __forceinline__ float2 u2f(u64 v) {
    float2 r; asm("mov.b64 {%0,%1}, %2;" : "=f"(r.x), "=f"(r.y) : "l"(v)); return r;
}
__device__ __forceinline__ float2 ffma2(float2 a, float2 b, float2 c) {
    u64 d;
    asm("fma.rn.f32x2 %0, %1, %2, %3;" : "=l"(d) : "l"(f2u(a)), "l"(f2u(b)), "l"(f2u(c)));
    return u2f(d);
}
__device__ __forceinline__ float2 fmul2(float2 a, float2 b) {
    u64 d;
    asm("mul.rn.f32x2 %0, %1, %2;" : "=l"(d) : "l"(f2u(a)), "l"(f2u(b)));
    return u2f(d);
}

// Folded parameters. All weight arrays 16B-aligned for LDS.128.
struct __align__(16) Params {
    float minv[L*L][8];
    float w1nb[16][16];
    float w1eg[16][16];
    float b1[16];
    float w2[8][16];
    float b2[8];
    float w3[4][8];
    float b3[4];
    float w4[4];
    float b4;
    float _pad[3];
    float wm[16][16];
    float bm[16];
};
__device__ Params g_p;

// HWC fp16 copy of x: per pixel, 16 channels = 32 bytes contiguous. 10.5 MB.
__device__ __half2 g_xt[(size_t)L * HW * 8];

// Fused transpose + param prep. Blocks [0, L*HW/256) transpose; last block preps.
__global__ __launch_bounds__(256)
void prep_transpose_kernel(
    const float* __restrict__ x,
    const float* __restrict__ ptm,
    const float* __restrict__ w1, const float* __restrict__ b1,
    const float* __restrict__ g1, const float* __restrict__ be1,
    const float* __restrict__ rm1, const float* __restrict__ rv1,
    const float* __restrict__ w2, const float* __restrict__ b2,
    const float* __restrict__ g2, const float* __restrict__ be2,
    const float* __restrict__ rm2, const float* __restrict__ rv2,
    const float* __restrict__ w3, const float* __restrict__ b3,
    const float* __restrict__ g3, const float* __restrict__ be3,
    const float* __restrict__ rm3, const float* __restrict__ rv3,
    const float* __restrict__ w4, const float* __restrict__ b4,
    const float* __restrict__ wm, const float* __restrict__ bm)
{
    if (blockIdx.x < (L*HW)/256) {
        int idx = blockIdx.x * 256 + threadIdx.x;   // over L*HW
        int j   = idx >> 16;
        int hw  = idx & (HW - 1);
        const float* base = x + (size_t)j * C * HW + hw;

        __half2 v[8];
        #pragma unroll
        for (int k = 0; k < 8; k++) {
            float a = __ldg(base + (2*k)   * HW);
            float b = __ldg(base + (2*k+1) * HW);
            v[k] = __floats2half2_rn(a, b);
        }
        uint4* dst = reinterpret_cast<uint4*>(g_xt) + (size_t)idx * 2;
        dst[0] = reinterpret_cast<uint4*>(v)[0];
        dst[1] = reinterpret_cast<uint4*>(v)[1];
        return;
    }

    // ---- parameter folding (last block) ----
    for (int t = threadIdx.x; t < 768; t += 256) {
        if (t < L*L) {
            const float* m = ptm + t*16;
            float a  = m[0], b = m[1], tx = m[3] * 1.25f;   // 1/(0.4*2)
            float c  = m[4], d = m[5], ty = m[7] * 1.25f;
            float inv = 1.0f / (a*d - b*c);
            float ia =  d*inv, ib = -b*inv;
            float ic = -c*inv, id =  a*inv;
            g_p.minv[t][0] = ia; g_p.minv[t][1] = ib; g_p.minv[t][2] = -(ia*tx + ib*ty);
            g_p.minv[t][3] = ic; g_p.minv[t][4] = id; g_p.minv[t][5] = -(ic*tx + id*ty);
            g_p.minv[t][6] = 0.f; g_p.minv[t][7] = 0.f;
        }
        if (t >= 32 && t < 288) {
            int idx2 = t - 32, o = idx2 >> 4, c2 = idx2 & 15;
            float sc = g1[o] * rsqrtf(rv1[o] + BN_EPS);
            g_p.w1nb[o][c2] = w1[o*32 + c2]      * sc;
            g_p.w1eg[o][c2] = w1[o*32 + 16 + c2] * sc;
            if (c2 == 0) g_p.b1[o] = (b1[o] - rm1[o]) * sc + be1[o];
        }
        if (t >= 288 && t < 416) {
            int idx2 = t - 288, o = idx2 >> 4, c2 = idx2 & 15;
            float sc = g2[o] * rsqrtf(rv2[o] + BN_EPS);
            g_p.w2[o][c2] = w2[o*16 + c2] * sc;
            if (c2 == 0) g_p.b2[o] = (b2[o] - rm2[o]) * sc + be2[o];
        }
        if (t >= 416 && t < 448) {
            int idx2 = t - 416, o = idx2 >> 3, c2 = idx2 & 7;
            float sc = g3[o] * rsqrtf(rv3[o] + BN_EPS);
            g_p.w3[o][c2] = w3[o*8 + c2] * sc;
            if (c2 == 0) g_p.b3[o] = (b3[o] - rm3[o]) * sc + be3[o];
        }
        if (t >= 448 && t < 452) g_p.w4[t-448] = w4[t-448];
        if (t == 452) g_p.b4 = b4[0];
        if (t >= 512 && t < 768) {
            int idx2 = t - 512, o = idx2 >> 4, c2 = idx2 & 15;
            g_p.wm[o][c2] = wm[o*16 + c2];
            if (c2 == 0) g_p.bm[o] = bm[o];
        }
    }
}

// Accumulate one tap (16 ch as 2 x uint4 of half2) into nb2[8] with weight w.
__device__ __forceinline__ void acc_tap2(uint4 va, uint4 vb, float w, float2* nb2)
{
    float2 wv = make_float2(w, w);
    #pragma unroll
    for (int k = 0; k < 4; k++) {
        float2 f = __half22float2(reinterpret_cast<__half2*>(&va)[k]);
        nb2[k] = ffma2(wv, f, nb2[k]);
    }
    #pragma unroll
    for (int k = 0; k < 4; k++) {
        float2 f = __half22float2(reinterpret_cast<__half2*>(&vb)[k]);
        nb2[4+k] = ffma2(wv, f, nb2[4+k]);
    }
}

// Dual dot: one 16-wide weight row against TWO packed input vectors.
// 4 x LDS.128 amortized over both pixels; returns (dot(a), dot(b)).
__device__ __forceinline__ float2 dot16_dual(const float* row,
                                             const float2* a, const float2* b)
{
    const float4* wr = reinterpret_cast<const float4*>(row);
    float2 sA = make_float2(0.f, 0.f), sB = make_float2(0.f, 0.f);
    #pragma unroll
    for (int q = 0; q < 4; q++) {
        float4 wv = wr[q];
        float2 w01 = make_float2(wv.x, wv.y), w23 = make_float2(wv.z, wv.w);
        sA = ffma2(w01, a[2*q],   sA);
        sA = ffma2(w23, a[2*q+1], sA);
        sB = ffma2(w01, b[2*q],   sB);
        sB = ffma2(w23, b[2*q+1], sB);
    }
    return make_float2(sA.x + sA.y, sB.x + sB.y);
}

// Dual dot, 8-wide row.
__device__ __forceinline__ float2 dot8_dual(const float* row,
                                            const float2* a, const float2* b)
{
    const float4* wr = reinterpret_cast<const float4*>(row);
    float2 sA = make_float2(0.f, 0.f), sB = make_float2(0.f, 0.f);
    #pragma unroll
    for (int q = 0; q < 2; q++) {
        float4 wv = wr[q];
        float2 w01 = make_float2(wv.x, wv.y), w23 = make_float2(wv.z, wv.w);
        sA = ffma2(w01, a[2*q],   sA);
        sA = ffma2(w23, a[2*q+1], sA);
        sB = ffma2(w01, b[2*q],   sB);
        sB = ffma2(w23, b[2*q+1], sB);
    }
    return make_float2(sA.x + sA.y, sB.x + sB.y);
}

// Per-j tap addresses + bilinear weights.
struct Tap {
    const uint4* p[4];
    float w[4];
};

__device__ __forceinline__ Tap calc_tap(const float* mv, float wf, float hf,
                                        const uint4* jb)
{
    Tap t;
    float sx = fmaf(mv[0], wf, fmaf(mv[1], hf, mv[2]));
    float sy = fmaf(mv[3], wf, fmaf(mv[4], hf, mv[5]));
    float x0f = floorf(sx), y0f = floorf(sy);
    float fx = sx - x0f, fy = sy - y0f;
    float w00 = (1.0f-fx)*(1.0f-fy), w01 = fx*(1.0f-fy);
    float w10 = (1.0f-fx)*fy,        w11 = fx*fy;
    int x0 = (int)x0f, y0 = (int)y0f;
    bool vx0 = (x0   >= 0) && (x0   <= W-1);
    bool vx1 = (x0+1 >= 0) && (x0+1 <= W-1);
    bool vy0 = (y0   >= 0) && (y0   <= H-1);
    bool vy1 = (y0+1 >= 0) && (y0+1 <= H-1);
    t.w[0] = (vx0 && vy0) ? w00 : 0.0f;
    t.w[1] = (vx1 && vy0) ? w01 : 0.0f;
    t.w[2] = (vx0 && vy1) ? w10 : 0.0f;
    t.w[3] = (vx1 && vy1) ? w11 : 0.0f;
    int xi0 = min(max(x0,   0), W-1), xi1 = min(max(x0+1, 0), W-1);
    int yi0 = min(max(y0,   0), H-1), yi1 = min(max(y0+1, 0), H-1);
    t.p[0] = jb + (size_t)(yi0*W + xi0) * 2;
    t.p[1] = jb + (size_t)(yi0*W + xi1) * 2;
    t.p[2] = jb + (size_t)(yi1*W + xi0) * 2;
    t.p[3] = jb + (size_t)(yi1*W + xi1) * 2;
    return t;
}

__global__ __launch_bounds__(128, 2)
void DiscoNetFusion_kernel(float* __restrict__ out)
{
    __shared__ Params sp;
    {
        const float4* src = (const float4*)&g_p;
        float4* dst = (float4*)&sp;
        const int n = sizeof(Params) / 16;
        for (int k = threadIdx.x; k < n; k += blockDim.x) dst[k] = src[k];
    }
    __syncthreads();

    const int i   = blockIdx.y;
    const int hw0 = (blockIdx.x * blockDim.x + threadIdx.x) * 2;  // even; pair {hw0, hw0+1}
    const float wf0 = (float)(hw0 & (W-1));
    const float hf  = (float)(hw0 >> 8);

    const uint4* xt = reinterpret_cast<const uint4*>(g_xt);

    // ---- ego for both pixels: 4 contiguous LDG.128 ----
    const uint4* pe = xt + (size_t)(i*HW + hw0) * 2;
    uint4 ea0 = __ldg(pe),     ea1 = __ldg(pe + 1);
    uint4 eb0 = __ldg(pe + 2), eb1 = __ldg(pe + 3);

    float eg0[16], eg1[16];
    {
        float2 xa[8], xb[8];
        #pragma unroll
        for (int k = 0; k < 4; k++) {
            xa[k]   = __half22float2(reinterpret_cast<__half2*>(&ea0)[k]);
            xa[4+k] = __half22float2(reinterpret_cast<__half2*>(&ea1)[k]);
            xb[k]   = __half22float2(reinterpret_cast<__half2*>(&eb0)[k]);
            xb[4+k] = __half22float2(reinterpret_cast<__half2*>(&eb1)[k]);
        }
        #pragma unroll
        for (int o = 0; o < 16; o++) {
            float2 d = dot16_dual(sp.w1eg[o], xa, xb);
            eg0[o] = d.x + sp.b1[o];
            eg1[o] = d.y + sp.b1[o];
        }
    }

    // ---- online softmax state (per pixel) ----
    float mr0 = -1e30f, sr0 = 0.0f, mr1 = -1e30f, sr1 = 0.0f;
    float2 acc0[8], acc1[8];
    #pragma unroll
    for (int k = 0; k < 8; k++) { acc0[k] = make_float2(0.f, 0.f); acc1[k] = make_float2(0.f, 0.f); }

    #pragma unroll 1
    for (int j = 0; j < L; j++) {
        const float* mv = sp.minv[j*L + i];
        const uint4* jb = xt + (size_t)j * HW * 2;

        // issue all 16 tap loads for both pixels, then fold
        Tap ta = calc_tap(mv, wf0,        hf, jb);
        Tap tb = calc_tap(mv, wf0 + 1.0f, hf, jb);

        uint4 rA0[4], rB0[4], rA1[4], rB1[4];
        #pragma unroll
        for (int t = 0; t < 4; t++) { rA0[t] = __ldg(ta.p[t]); rB0[t] = __ldg(ta.p[t] + 1); }
        #pragma unroll
        for (int t = 0; t < 4; t++) { rA1[t] = __ldg(tb.p[t]); rB1[t] = __ldg(tb.p[t] + 1); }

        float2 nb0[8], nb1[8];
        #pragma unroll
        for (int k = 0; k < 8; k++) { nb0[k] = make_float2(0.f, 0.f); nb1[k] = make_float2(0.f, 0.f); }
        #pragma unroll
        for (int t = 0; t < 4; t++) acc_tap2(rA0[t], rB0[t], ta.w[t], nb0);
        #pragma unroll
        for (int t = 0; t < 4; t++) acc_tap2(rA1[t], rB1[t], tb.w[t], nb1);

        // ---- dual-pixel MLP (weights loaded once per row) ----
        float2 h1a[8], h1b[8];
        #pragma unroll
        for (int o = 0; o < 8; o++) {
            float2 dA = dot16_dual(sp.w1nb[2*o],   nb0, nb1);   // (px0, px1) row 2o
            float2 dB = dot16_dual(sp.w1nb[2*o+1], nb0, nb1);   // (px0, px1) row 2o+1
            h1a[o] = make_float2(fmaxf(dA.x + eg0[2*o],   0.f), fmaxf(dB.x + eg0[2*o+1], 0.f));
            h1b[o] = make_float2(fmaxf(dA.y + eg1[2*o],   0.f), fmaxf(dB.y + eg1[2*o+1], 0.f));
        }
        float2 h2a[4], h2b[4];
        #pragma unroll
        for (int o = 0; o < 4; o++) {
            float2 dA = dot16_dual(sp.w2[2*o],   h1a, h1b);
            float2 dB = dot16_dual(sp.w2[2*o+1], h1a, h1b);
            h2a[o] = make_float2(fmaxf(dA.x + sp.b2[2*o], 0.f), fmaxf(dB.x + sp.b2[2*o+1], 0.f));
            h2b[o] = make_float2(fmaxf(dA.y + sp.b2[2*o], 0.f), fmaxf(dB.y + sp.b2[2*o+1], 0.f));
        }
        float2 h3a[2], h3b[2];
        #pragma unroll
        for (int o = 0; o < 4; o++) {
            float2 d = dot8_dual(sp.w3[o], h2a, h2b);
            float v0 = fmaxf(d.x + sp.b3[o], 0.f);
            float v1 = fmaxf(d.y + sp.b3[o], 0.f);
            if (o & 1) { h3a[o>>1].y = v0; h3b[o>>1].y = v1; }
            else       { h3a[o>>1].x = v0; h3b[o>>1].x = v1; }
        }
        float2 wa = make_float2(sp.w4[0], sp.w4[1]);
        float2 wb = make_float2(sp.w4[2], sp.w4[3]);
        float2 l0 = ffma2(wa, h3a[0], fmul2(wb, h3a[1]));
        float2 l1 = ffma2(wa, h3b[0], fmul2(wb, h3b[1]));
        float lg0 = fmaxf(l0.x + l0.y + sp.b4, 0.0f);
        float lg1 = fmaxf(l1.x + l1.y + sp.b4, 0.0f);

        // ---- online softmax accumulate, both pixels ----
        {
            float mn = fmaxf(mr0, lg0);
            float scl = __expf(mr0 - mn), p = __expf(lg0 - mn);
            sr0 = sr0 * scl + p;
            float2 sv = make_float2(scl, scl), pv = make_float2(p, p);
            #pragma unroll
            for (int k = 0; k < 8; k++) acc0[k] = ffma2(acc0[k], sv, fmul2(pv, nb0[k]));
            mr0 = mn;
        }
        {
            float mn = fmaxf(mr1, lg1);
            float scl = __expf(mr1 - mn), p = __expf(lg1 - mn);
            sr1 = sr1 * scl + p;
            float2 sv = make_float2(scl, scl), pv = make_float2(p, p);
            #pragma unroll
            for (int k = 0; k < 8; k++) acc1[k] = ffma2(acc1[k], sv, fmul2(pv, nb1[k]));
            mr1 = mn;
        }
    }

    {
        float iv0 = 1.0f / sr0, iv1 = 1.0f / sr1;
        float2 v0 = make_float2(iv0, iv0), v1 = make_float2(iv1, iv1);
        #pragma unroll
        for (int k = 0; k < 8; k++) { acc0[k] = fmul2(acc0[k], v0); acc1[k] = fmul2(acc1[k], v1); }
    }

    // ---- final 16x16 channel mix + bias; STG.64 per channel ----
    #pragma unroll
    for (int o = 0; o < 16; o++) {
        float2 d = dot16_dual(sp.wm[o], acc0, acc1);
        float2 st = make_float2(d.x + sp.bm[o], d.y + sp.bm[o]);
        *reinterpret_cast<float2*>(out + (size_t)(i*C + o)*HW + hw0) = st;
    }
}

extern "C" void kernel_launch(void* const* d_in, const int* in_sizes, int n_in,
                              void* d_out, int out_size)
{
    (void)in_sizes; (void)n_in; (void)out_size;
    const float* x   = (const float*)d_in[0];
    // d_in[1] = record_len (unused)
    const float* ptm = (const float*)d_in[2];

    prep_transpose_kernel<<<(L*HW)/256 + 1, 256>>>(x, ptm,
        (const float*)d_in[3],  (const float*)d_in[4],  (const float*)d_in[5],
        (const float*)d_in[6],  (const float*)d_in[7],  (const float*)d_in[8],
        (const float*)d_in[9],  (const float*)d_in[10], (const float*)d_in[11],
        (const float*)d_in[12], (const float*)d_in[13], (const float*)d_in[14],
        (const float*)d_in[15], (const float*)d_in[16], (const float*)d_in[17],
        (const float*)d_in[18], (const float*)d_in[19], (const float*)d_in[20],
        (const float*)d_in[21], (const float*)d_in[22],
        (const float*)d_in[23], (const float*)d_in[24]);

    dim3 grid(HW / 256, L);   // 2 pixels per thread, 128 threads per block
    DiscoNetFusion_kernel<<<grid, 128>>>((float*)d_out);
}

// round 15
// speedup vs baseline: 3.6272x; 1.1202x over previous
#include <cuda_runtime.h>
#include <cuda_fp16.h>
#include <math.h>

#define L 5
#define C 16
#define H 256
#define W 256
#define HW (H*W)
#define BN_EPS 1e-5f

typedef unsigned long long u64;

// ---- packed fp32x2 helpers (Blackwell FFMA2 path) ----
__device__ __forceinline__ u64 f2u(float2 v) {
    u64 r; asm("mov.b64 %0, {%1,%2};" : "=l"(r) : "f"(v.x), "f"(v.y)); return r;
}
__device__ __forceinline__ float2 u2f(u64 v) {
    float2 r; asm("mov.b64 {%0,%1}, %2;" : "=f"(r.x), "=f"(r.y) : "l"(v)); return r;
}
__device__ __forceinline__ float2 ffma2(float2 a, float2 b, float2 c) {
    u64 d;
    asm("fma.rn.f32x2 %0, %1, %2, %3;" : "=l"(d) : "l"(f2u(a)), "l"(f2u(b)), "l"(f2u(c)));
    return u2f(d);
}
__device__ __forceinline__ float2 fmul2(float2 a, float2 b) {
    u64 d;
    asm("mul.rn.f32x2 %0, %1, %2;" : "=l"(d) : "l"(f2u(a)), "l"(f2u(b)));
    return u2f(d);
}

// Folded parameters. 16B-aligned rows.
struct __align__(16) Params {
    float minv[L*L][8];
    float w1nb[16][16];
    float w1eg[16][16];
    float b1[16];
    float w2[8][16];
    float b2[8];
    float w3[4][8];
    float b3[4];
    float w4[4];
    float b4;
    float _pad[3];
    float wm[16][16];
    float bm[16];
};
__device__ Params g_p;          // written by prep kernel
__constant__ Params c_p;        // copied from g_p; read by main kernel (LDCU path)

// HWC fp16 copy of x: per pixel, 16 channels = 32 bytes contiguous. 10.5 MB.
__device__ __half2 g_xt[(size_t)L * HW * 8];

// Fused transpose + param prep. Blocks [0, L*HW/256) transpose; last block preps.
__global__ __launch_bounds__(256)
void prep_transpose_kernel(
    const float* __restrict__ x,
    const float* __restrict__ ptm,
    const float* __restrict__ w1, const float* __restrict__ b1,
    const float* __restrict__ g1, const float* __restrict__ be1,
    const float* __restrict__ rm1, const float* __restrict__ rv1,
    const float* __restrict__ w2, const float* __restrict__ b2,
    const float* __restrict__ g2, const float* __restrict__ be2,
    const float* __restrict__ rm2, const float* __restrict__ rv2,
    const float* __restrict__ w3, const float* __restrict__ b3,
    const float* __restrict__ g3, const float* __restrict__ be3,
    const float* __restrict__ rm3, const float* __restrict__ rv3,
    const float* __restrict__ w4, const float* __restrict__ b4,
    const float* __restrict__ wm, const float* __restrict__ bm)
{
    if (blockIdx.x < (L*HW)/256) {
        int idx = blockIdx.x * 256 + threadIdx.x;   // over L*HW
        int j   = idx >> 16;
        int hw  = idx & (HW - 1);
        const float* base = x + (size_t)j * C * HW + hw;

        __half2 v[8];
        #pragma unroll
        for (int k = 0; k < 8; k++) {
            float a = __ldg(base + (2*k)   * HW);
            float b = __ldg(base + (2*k+1) * HW);
            v[k] = __floats2half2_rn(a, b);
        }
        uint4* dst = reinterpret_cast<uint4*>(g_xt) + (size_t)idx * 2;
        dst[0] = reinterpret_cast<uint4*>(v)[0];
        dst[1] = reinterpret_cast<uint4*>(v)[1];
        return;
    }

    // ---- parameter folding (last block) ----
    for (int t = threadIdx.x; t < 768; t += 256) {
        if (t < L*L) {
            const float* m = ptm + t*16;
            float a  = m[0], b = m[1], tx = m[3] * 1.25f;   // 1/(0.4*2)
            float c  = m[4], d = m[5], ty = m[7] * 1.25f;
            float inv = 1.0f / (a*d - b*c);
            float ia =  d*inv, ib = -b*inv;
            float ic = -c*inv, id =  a*inv;
            g_p.minv[t][0] = ia; g_p.minv[t][1] = ib; g_p.minv[t][2] = -(ia*tx + ib*ty);
            g_p.minv[t][3] = ic; g_p.minv[t][4] = id; g_p.minv[t][5] = -(ic*tx + id*ty);
            g_p.minv[t][6] = 0.f; g_p.minv[t][7] = 0.f;
        }
        if (t >= 32 && t < 288) {
            int idx2 = t - 32, o = idx2 >> 4, c2 = idx2 & 15;
            float sc = g1[o] * rsqrtf(rv1[o] + BN_EPS);
            g_p.w1nb[o][c2] = w1[o*32 + c2]      * sc;
            g_p.w1eg[o][c2] = w1[o*32 + 16 + c2] * sc;
            if (c2 == 0) g_p.b1[o] = (b1[o] - rm1[o]) * sc + be1[o];
        }
        if (t >= 288 && t < 416) {
            int idx2 = t - 288, o = idx2 >> 4, c2 = idx2 & 15;
            float sc = g2[o] * rsqrtf(rv2[o] + BN_EPS);
            g_p.w2[o][c2] = w2[o*16 + c2] * sc;
            if (c2 == 0) g_p.b2[o] = (b2[o] - rm2[o]) * sc + be2[o];
        }
        if (t >= 416 && t < 448) {
            int idx2 = t - 416, o = idx2 >> 3, c2 = idx2 & 7;
            float sc = g3[o] * rsqrtf(rv3[o] + BN_EPS);
            g_p.w3[o][c2] = w3[o*8 + c2] * sc;
            if (c2 == 0) g_p.b3[o] = (b3[o] - rm3[o]) * sc + be3[o];
        }
        if (t >= 448 && t < 452) g_p.w4[t-448] = w4[t-448];
        if (t == 452) g_p.b4 = b4[0];
        if (t >= 512 && t < 768) {
            int idx2 = t - 512, o = idx2 >> 4, c2 = idx2 & 15;
            g_p.wm[o][c2] = wm[o*16 + c2];
            if (c2 == 0) g_p.bm[o] = bm[o];
        }
    }
}

// Accumulate one tap (16 ch as 2 x uint4 of half2) into nb2[8] with weight w.
__device__ __forceinline__ void acc_tap2(uint4 va, uint4 vb, float w, float2* nb2)
{
    float2 wv = make_float2(w, w);
    #pragma unroll
    for (int k = 0; k < 4; k++) {
        float2 f = __half22float2(reinterpret_cast<__half2*>(&va)[k]);
        nb2[k] = ffma2(wv, f, nb2[k]);
    }
    #pragma unroll
    for (int k = 0; k < 4; k++) {
        float2 f = __half22float2(reinterpret_cast<__half2*>(&vb)[k]);
        nb2[4+k] = ffma2(wv, f, nb2[4+k]);
    }
}

// Dual dot: one 16-wide constant weight row against TWO packed input vectors.
__device__ __forceinline__ float2 dot16_dual(const float* row,
                                             const float2* a, const float2* b)
{
    const float4* wr = reinterpret_cast<const float4*>(row);
    float2 sA = make_float2(0.f, 0.f), sB = make_float2(0.f, 0.f);
    #pragma unroll
    for (int q = 0; q < 4; q++) {
        float4 wv = wr[q];
        float2 w01 = make_float2(wv.x, wv.y), w23 = make_float2(wv.z, wv.w);
        sA = ffma2(w01, a[2*q],   sA);
        sA = ffma2(w23, a[2*q+1], sA);
        sB = ffma2(w01, b[2*q],   sB);
        sB = ffma2(w23, b[2*q+1], sB);
    }
    return make_float2(sA.x + sA.y, sB.x + sB.y);
}

// Dual dot, 8-wide row.
__device__ __forceinline__ float2 dot8_dual(const float* row,
                                            const float2* a, const float2* b)
{
    const float4* wr = reinterpret_cast<const float4*>(row);
    float2 sA = make_float2(0.f, 0.f), sB = make_float2(0.f, 0.f);
    #pragma unroll
    for (int q = 0; q < 2; q++) {
        float4 wv = wr[q];
        float2 w01 = make_float2(wv.x, wv.y), w23 = make_float2(wv.z, wv.w);
        sA = ffma2(w01, a[2*q],   sA);
        sA = ffma2(w23, a[2*q+1], sA);
        sB = ffma2(w01, b[2*q],   sB);
        sB = ffma2(w23, b[2*q+1], sB);
    }
    return make_float2(sA.x + sA.y, sB.x + sB.y);
}

// Per-j tap addresses + bilinear weights.
struct Tap {
    const uint4* p[4];
    float w[4];
};

__device__ __forceinline__ Tap calc_tap(const float* mv, float wf, float hf,
                                        const uint4* jb)
{
    Tap t;
    float sx = fmaf(mv[0], wf, fmaf(mv[1], hf, mv[2]));
    float sy = fmaf(mv[3], wf, fmaf(mv[4], hf, mv[5]));
    float x0f = floorf(sx), y0f = floorf(sy);
    float fx = sx - x0f, fy = sy - y0f;
    float w00 = (1.0f-fx)*(1.0f-fy), w01 = fx*(1.0f-fy);
    float w10 = (1.0f-fx)*fy,        w11 = fx*fy;
    int x0 = (int)x0f, y0 = (int)y0f;
    bool vx0 = (x0   >= 0) && (x0   <= W-1);
    bool vx1 = (x0+1 >= 0) && (x0+1 <= W-1);
    bool vy0 = (y0   >= 0) && (y0   <= H-1);
    bool vy1 = (y0+1 >= 0) && (y0+1 <= H-1);
    t.w[0] = (vx0 && vy0) ? w00 : 0.0f;
    t.w[1] = (vx1 && vy0) ? w01 : 0.0f;
    t.w[2] = (vx0 && vy1) ? w10 : 0.0f;
    t.w[3] = (vx1 && vy1) ? w11 : 0.0f;
    int xi0 = min(max(x0,   0), W-1), xi1 = min(max(x0+1, 0), W-1);
    int yi0 = min(max(y0,   0), H-1), yi1 = min(max(y0+1, 0), H-1);
    t.p[0] = jb + (size_t)(yi0*W + xi0) * 2;
    t.p[1] = jb + (size_t)(yi0*W + xi1) * 2;
    t.p[2] = jb + (size_t)(yi1*W + xi0) * 2;
    t.p[3] = jb + (size_t)(yi1*W + xi1) * 2;
    return t;
}

__global__ __launch_bounds__(128, 2)
void DiscoNetFusion_kernel(float* __restrict__ out)
{
    const int i   = blockIdx.y;
    const int hw0 = (blockIdx.x * blockDim.x + threadIdx.x) * 2;  // pair {hw0, hw0+1}
    const float wf0 = (float)(hw0 & (W-1));
    const float hf  = (float)(hw0 >> 8);

    const uint4* xt = reinterpret_cast<const uint4*>(g_xt);

    // ---- ego for both pixels: 4 contiguous LDG.128 ----
    const uint4* pe = xt + (size_t)(i*HW + hw0) * 2;
    uint4 ea0 = __ldg(pe),     ea1 = __ldg(pe + 1);
    uint4 eb0 = __ldg(pe + 2), eb1 = __ldg(pe + 3);

    float eg0[16], eg1[16];
    {
        float2 xa[8], xb[8];
        #pragma unroll
        for (int k = 0; k < 4; k++) {
            xa[k]   = __half22float2(reinterpret_cast<__half2*>(&ea0)[k]);
            xa[4+k] = __half22float2(reinterpret_cast<__half2*>(&ea1)[k]);
            xb[k]   = __half22float2(reinterpret_cast<__half2*>(&eb0)[k]);
            xb[4+k] = __half22float2(reinterpret_cast<__half2*>(&eb1)[k]);
        }
        #pragma unroll
        for (int o = 0; o < 16; o++) {
            float2 d = dot16_dual(c_p.w1eg[o], xa, xb);
            eg0[o] = d.x + c_p.b1[o];
            eg1[o] = d.y + c_p.b1[o];
        }
    }

    // ---- online softmax state (per pixel) ----
    float mr0 = -1e30f, sr0 = 0.0f, mr1 = -1e30f, sr1 = 0.0f;
    float2 acc0[8], acc1[8];
    #pragma unroll
    for (int k = 0; k < 8; k++) { acc0[k] = make_float2(0.f, 0.f); acc1[k] = make_float2(0.f, 0.f); }

    #pragma unroll 1
    for (int j = 0; j < L; j++) {
        const float* mv = c_p.minv[j*L + i];
        const uint4* jb = xt + (size_t)j * HW * 2;

        // issue all 16 tap loads for both pixels, then fold
        Tap ta = calc_tap(mv, wf0,        hf, jb);
        Tap tb = calc_tap(mv, wf0 + 1.0f, hf, jb);

        uint4 rA0[4], rB0[4], rA1[4], rB1[4];
        #pragma unroll
        for (int t = 0; t < 4; t++) { rA0[t] = __ldg(ta.p[t]); rB0[t] = __ldg(ta.p[t] + 1); }
        #pragma unroll
        for (int t = 0; t < 4; t++) { rA1[t] = __ldg(tb.p[t]); rB1[t] = __ldg(tb.p[t] + 1); }

        float2 nb0[8], nb1[8];
        #pragma unroll
        for (int k = 0; k < 8; k++) { nb0[k] = make_float2(0.f, 0.f); nb1[k] = make_float2(0.f, 0.f); }
        #pragma unroll
        for (int t = 0; t < 4; t++) acc_tap2(rA0[t], rB0[t], ta.w[t], nb0);
        #pragma unroll
        for (int t = 0; t < 4; t++) acc_tap2(rA1[t], rB1[t], tb.w[t], nb1);

        // ---- dual-pixel MLP (weights from constant bank) ----
        float2 h1a[8], h1b[8];
        #pragma unroll
        for (int o = 0; o < 8; o++) {
            float2 dA = dot16_dual(c_p.w1nb[2*o],   nb0, nb1);
            float2 dB = dot16_dual(c_p.w1nb[2*o+1], nb0, nb1);
            h1a[o] = make_float2(fmaxf(dA.x + eg0[2*o],   0.f), fmaxf(dB.x + eg0[2*o+1], 0.f));
            h1b[o] = make_float2(fmaxf(dA.y + eg1[2*o],   0.f), fmaxf(dB.y + eg1[2*o+1], 0.f));
        }
        float2 h2a[4], h2b[4];
        #pragma unroll
        for (int o = 0; o < 4; o++) {
            float2 dA = dot16_dual(c_p.w2[2*o],   h1a, h1b);
            float2 dB = dot16_dual(c_p.w2[2*o+1], h1a, h1b);
            h2a[o] = make_float2(fmaxf(dA.x + c_p.b2[2*o], 0.f), fmaxf(dB.x + c_p.b2[2*o+1], 0.f));
            h2b[o] = make_float2(fmaxf(dA.y + c_p.b2[2*o], 0.f), fmaxf(dB.y + c_p.b2[2*o+1], 0.f));
        }
        float2 h3a[2], h3b[2];
        #pragma unroll
        for (int o = 0; o < 4; o++) {
            float2 d = dot8_dual(c_p.w3[o], h2a, h2b);
            float v0 = fmaxf(d.x + c_p.b3[o], 0.f);
            float v1 = fmaxf(d.y + c_p.b3[o], 0.f);
            if (o & 1) { h3a[o>>1].y = v0; h3b[o>>1].y = v1; }
            else       { h3a[o>>1].x = v0; h3b[o>>1].x = v1; }
        }
        float2 wa = make_float2(c_p.w4[0], c_p.w4[1]);
        float2 wb = make_float2(c_p.w4[2], c_p.w4[3]);
        float2 l0 = ffma2(wa, h3a[0], fmul2(wb, h3a[1]));
        float2 l1 = ffma2(wa, h3b[0], fmul2(wb, h3b[1]));
        float lg0 = fmaxf(l0.x + l0.y + c_p.b4, 0.0f);
        float lg1 = fmaxf(l1.x + l1.y + c_p.b4, 0.0f);

        // ---- online softmax accumulate, both pixels ----
        {
            float mn = fmaxf(mr0, lg0);
            float scl = __expf(mr0 - mn), p = __expf(lg0 - mn);
            sr0 = sr0 * scl + p;
            float2 sv = make_float2(scl, scl), pv = make_float2(p, p);
            #pragma unroll
            for (int k = 0; k < 8; k++) acc0[k] = ffma2(acc0[k], sv, fmul2(pv, nb0[k]));
            mr0 = mn;
        }
        {
            float mn = fmaxf(mr1, lg1);
            float scl = __expf(mr1 - mn), p = __expf(lg1 - mn);
            sr1 = sr1 * scl + p;
            float2 sv = make_float2(scl, scl), pv = make_float2(p, p);
            #pragma unroll
            for (int k = 0; k < 8; k++) acc1[k] = ffma2(acc1[k], sv, fmul2(pv, nb1[k]));
            mr1 = mn;
        }
    }

    {
        float iv0 = 1.0f / sr0, iv1 = 1.0f / sr1;
        float2 v0 = make_float2(iv0, iv0), v1 = make_float2(iv1, iv1);
        #pragma unroll
        for (int k = 0; k < 8; k++) { acc0[k] = fmul2(acc0[k], v0); acc1[k] = fmul2(acc1[k], v1); }
    }

    // ---- final 16x16 channel mix + bias; STG.64 per channel ----
    #pragma unroll
    for (int o = 0; o < 16; o++) {
        float2 d = dot16_dual(c_p.wm[o], acc0, acc1);
        float2 st = make_float2(d.x + c_p.bm[o], d.y + c_p.bm[o]);
        *reinterpret_cast<float2*>(out + (size_t)(i*C + o)*HW + hw0) = st;
    }
}

extern "C" void kernel_launch(void* const* d_in, const int* in_sizes, int n_in,
                              void* d_out, int out_size)
{
    (void)in_sizes; (void)n_in; (void)out_size;
    const float* x   = (const float*)d_in[0];
    // d_in[1] = record_len (unused)
    const float* ptm = (const float*)d_in[2];

    prep_transpose_kernel<<<(L*HW)/256 + 1, 256>>>(x, ptm,
        (const float*)d_in[3],  (const float*)d_in[4],  (const float*)d_in[5],
        (const float*)d_in[6],  (const float*)d_in[7],  (const float*)d_in[8],
        (const float*)d_in[9],  (const float*)d_in[10], (const float*)d_in[11],
        (const float*)d_in[12], (const float*)d_in[13], (const float*)d_in[14],
        (const float*)d_in[15], (const float*)d_in[16], (const float*)d_in[17],
        (const float*)d_in[18], (const float*)d_in[19], (const float*)d_in[20],
        (const float*)d_in[21], (const float*)d_in[22],
        (const float*)d_in[23], (const float*)d_in[24]);

    // Stage folded params into the constant bank (D2D async, graph-capturable).
    void* gp_addr = nullptr;
    cudaGetSymbolAddress(&gp_addr, g_p);
    cudaMemcpyToSymbolAsync(c_p, gp_addr, sizeof(Params), 0,
                            cudaMemcpyDeviceToDevice, 0);

    dim3 grid(HW / 256, L);   // 2 pixels per thread, 128 threads per block
    DiscoNetFusion_kernel<<<grid, 128>>>((float*)d_out);
}